// round 1
// baseline (speedup 1.0000x reference)
#include <cuda_runtime.h>
#include <cstdint>

// ---------------- static scratch (no runtime allocation allowed) ----------------
#define NMAXN   131072
#define EMAXE   2200000
#define PMAXP   32768
#define CMAXC   256
#define BMAXB   64
#define HBITS   22
#define HSIZE   (1u << HBITS)
#define PAIRMAX 2097152
#define HEMPTY  0xFFFFFFFFFFFFFFFFull

__device__ float              g_z[NMAXN];
__device__ float              g_e[NMAXN];
__device__ int                g_notpeak[NMAXN];
__device__ int                g_visit[NMAXN];
__device__ int                g_outdeg[NMAXN];
__device__ int                g_rowoff[NMAXN + 1];
__device__ int                g_fillpos[NMAXN];
__device__ int                g_peakrank[NMAXN];
__device__ int                g_col[EMAXE];
__device__ uint2              g_pairs[PAIRMAX];
__device__ unsigned long long g_htab[HSIZE];
__device__ unsigned           g_maxx[(size_t)PMAXP * CMAXC];
__device__ unsigned           g_maxelev[PMAXP];
__device__ int                g_peaknode[PMAXP];
__device__ int                g_cbv[PMAXP];
__device__ float              g_exn[PMAXP];
__device__ unsigned           g_bmaxz[BMAXB];   // per-batch max(z), encoded
__device__ float              g_bsum[BMAXB];    // per-batch sum(exp(z-m))
__device__ unsigned           g_cbmax[BMAXB];   // per-batch max(max_elev), encoded
__device__ float              g_cbsum[BMAXB];
__device__ int                g_bs[1024];       // scan block sums
__device__ int                g_nP;             // number of peaks / clusters
__device__ int                g_nEdesc;         // number of descending edges
__device__ int                g_is64;           // 1 if index dtype is int64

struct Ctr { int pair_tail; int bar_count; int bar_gen; };
__device__ Ctr g_ctr;

// ---------------- helpers ----------------
__device__ __forceinline__ unsigned encf(float f) {
    unsigned u = __float_as_uint(f);
    return (u & 0x80000000u) ? ~u : (u | 0x80000000u);
}
__device__ __forceinline__ float decf(unsigned u) {
    return __uint_as_float((u & 0x80000000u) ? (u ^ 0x80000000u) : ~u);
}
__device__ __forceinline__ long long ld_idx(const void* p, long long i, int is64) {
    if (is64) return ((const long long*)p)[i];
    return (long long)((const int*)p)[i];
}

// ---------------- dtype sniff ----------------
__global__ void k_sniff(const void* ei, int E, int N) {
    __shared__ int ok;
    if (threadIdx.x == 0) ok = 1;
    __syncthreads();
    int ncheck = E < 512 ? E : 512;
    for (int i = threadIdx.x; i < ncheck; i += blockDim.x) {
        long long v = ((const long long*)ei)[i];
        if (v < 0 || v >= (long long)N) atomicExch(&ok, 0);
    }
    __syncthreads();
    if (threadIdx.x == 0) g_is64 = ok;
}

// ---------------- z = x @ W^T + b, per-batch max(z) ----------------
__global__ void k_z(const float* __restrict__ x, const float* __restrict__ W,
                    const float* __restrict__ bb, const void* batch, int N, int C) {
    __shared__ unsigned s_bmax[BMAXB];
    if (threadIdx.x < BMAXB) s_bmax[threadIdx.x] = 0u;
    __syncthreads();
    int is64 = g_is64;
    int gwarp = (blockIdx.x * blockDim.x + threadIdx.x) >> 5;
    int lane  = threadIdx.x & 31;
    int nw    = (gridDim.x * blockDim.x) >> 5;
    for (int n = gwarp; n < N; n += nw) {
        const float* xr = x + (size_t)n * C;
        double acc = 0.0;
        for (int i = lane; i < C; i += 32) acc += (double)xr[i] * (double)W[i];
        #pragma unroll
        for (int o = 16; o > 0; o >>= 1) acc += __shfl_down_sync(0xffffffffu, acc, o);
        if (lane == 0) {
            float zf = (float)acc + bb[0];
            g_z[n] = zf;
            int bt = (int)ld_idx(batch, n, is64);
            if (bt >= 0 && bt < BMAXB) atomicMax(&s_bmax[bt], encf(zf));
        }
    }
    __syncthreads();
    if (threadIdx.x < BMAXB && s_bmax[threadIdx.x] != 0u)
        atomicMax(&g_bmaxz[threadIdx.x], s_bmax[threadIdx.x]);
}

// ---------------- e = exp(z - m[batch]); s[batch] += e ----------------
__global__ void k_exp(const void* batch, int N) {
    __shared__ float ssum[BMAXB];
    if (threadIdx.x < BMAXB) ssum[threadIdx.x] = 0.f;
    __syncthreads();
    int is64 = g_is64;
    int n = blockIdx.x * blockDim.x + threadIdx.x;
    if (n < N) {
        int bt = (int)ld_idx(batch, n, is64);
        float m = decf(g_bmaxz[bt]);
        float ev = expf(g_z[n] - m);
        g_e[n] = ev;
        atomicAdd(&ssum[bt], ev);
    }
    __syncthreads();
    if (threadIdx.x < BMAXB && ssum[threadIdx.x] != 0.f)
        atomicAdd(&g_bsum[threadIdx.x], ssum[threadIdx.x]);
}

// ---------------- peak flags + descending out-degree ----------------
__global__ void k_edges(const void* ei, int E) {
    int is64 = g_is64;
    int e = blockIdx.x * blockDim.x + threadIdx.x;
    if (e >= E) return;
    int ls = (int)ld_idx(ei, e, is64);
    int ld = (int)ld_idx(ei, (long long)E + e, is64);
    float zs = g_z[ls], zd = g_z[ld];
    if (zd < zs) g_notpeak[ld] = 1;            // dst has a strictly higher in-neighbor
    if (zd <= zs) atomicAdd(&g_outdeg[ls], 1); // descending edge ls -> ld
}

// ---------------- generic exclusive scan (3 kernels) ----------------
__global__ void k_scan_partial(const int* __restrict__ in, int n, int mode,
                               int* __restrict__ out, int* __restrict__ bsums) {
    __shared__ int sh[1024];
    int gid = blockIdx.x * 1024 + threadIdx.x;
    int v = 0;
    if (gid < n) { int t = in[gid]; v = mode ? (t == 0 ? 1 : 0) : t; }
    sh[threadIdx.x] = v;
    __syncthreads();
    for (int off = 1; off < 1024; off <<= 1) {
        int t = 0;
        if (threadIdx.x >= off) t = sh[threadIdx.x - off];
        __syncthreads();
        if (threadIdx.x >= off) sh[threadIdx.x] += t;
        __syncthreads();
    }
    if (gid < n) out[gid] = sh[threadIdx.x] - v;
    if (threadIdx.x == 1023) bsums[blockIdx.x] = sh[1023];
}
__global__ void k_scan_bsums(int* bsums, int nb, int* total) {
    __shared__ int sh[1024];
    int v = (threadIdx.x < nb) ? bsums[threadIdx.x] : 0;
    sh[threadIdx.x] = v;
    __syncthreads();
    for (int off = 1; off < 1024; off <<= 1) {
        int t = 0;
        if (threadIdx.x >= off) t = sh[threadIdx.x - off];
        __syncthreads();
        if (threadIdx.x >= off) sh[threadIdx.x] += t;
        __syncthreads();
    }
    if (threadIdx.x < nb) bsums[threadIdx.x] = sh[threadIdx.x] - v;
    if (threadIdx.x == 1023) *total = sh[1023];
}
__global__ void k_scan_add(int* out, int n, const int* __restrict__ bsums) {
    int gid = blockIdx.x * 1024 + threadIdx.x;
    if (gid < n) out[gid] += bsums[blockIdx.x];
}

// ---------------- peak list, visit init, CSR fill cursor, counters ----------------
__global__ void k_peaklist(const void* batch, int N) {
    int is64 = g_is64;
    int n = blockIdx.x * blockDim.x + threadIdx.x;
    if (n == 0) {
        int P = g_nP; if (P > PMAXP) P = PMAXP;
        g_ctr.pair_tail = P;
        g_ctr.bar_count = 0;
        g_ctr.bar_gen = 0;
        g_rowoff[N] = g_nEdesc;
    }
    if (n >= N) return;
    g_fillpos[n] = g_rowoff[n];
    if (!g_notpeak[n]) {
        int r = g_peakrank[n];
        g_visit[n] = 0;
        if (r < PMAXP) {
            g_peaknode[r] = n;
            g_cbv[r] = (int)ld_idx(batch, n, is64);
            g_pairs[r] = make_uint2((unsigned)n, (unsigned)r);
        }
    }
}

// ---------------- CSR column fill ----------------
__global__ void k_csrfill(const void* ei, int E) {
    int is64 = g_is64;
    int e = blockIdx.x * blockDim.x + threadIdx.x;
    if (e >= E) return;
    int ls = (int)ld_idx(ei, e, is64);
    int ld = (int)ld_idx(ei, (long long)E + e, is64);
    if (g_z[ld] <= g_z[ls]) {
        int pos = atomicAdd(&g_fillpos[ls], 1);
        if (pos < EMAXE) g_col[pos] = ld;
    }
}

// ---------------- persistent BFS with software grid barrier ----------------
__device__ __forceinline__ void grid_barrier(int nblocks) {
    __threadfence();
    __syncthreads();
    if (threadIdx.x == 0) {
        volatile int* genp = &g_ctr.bar_gen;
        int g = *genp;
        if (atomicAdd(&g_ctr.bar_count, 1) == nblocks - 1) {
            g_ctr.bar_count = 0;
            __threadfence();
            *genp = g + 1;
        } else {
            while (*genp == g) { __nanosleep(64); }
        }
        __threadfence();
    }
    __syncthreads();
}

__global__ void __launch_bounds__(256) k_bfs(int nblocks) {
    int lo = 0;
    int hi = g_nP; if (hi > PMAXP) hi = PMAXP;
    int L = 1;
    while (hi > lo && L < 200000) {
        int stride = nblocks * (int)blockDim.x;
        for (int i = lo + blockIdx.x * (int)blockDim.x + (int)threadIdx.x; i < hi; i += stride) {
            uint2 pr = g_pairs[i];
            int u = (int)pr.x;
            unsigned c = pr.y;
            int beg = g_rowoff[u], end = g_rowoff[u + 1];
            for (int j = beg; j < end; j++) {
                int v = g_col[j];
                if (g_visit[v] < L) continue;   // already claimed by earlier level
                unsigned long long key = ((unsigned long long)(unsigned)v << 32) | c;
                unsigned long long h = key * 0x9E3779B97F4A7C15ull;
                h ^= h >> 33; h *= 0xff51afd7ed558ccdull; h ^= h >> 33;
                unsigned slot = (unsigned)h & (HSIZE - 1);
                bool inserted = false;
                while (true) {
                    unsigned long long prev = atomicCAS(&g_htab[slot], HEMPTY, key);
                    if (prev == HEMPTY) { inserted = true; break; }
                    if (prev == key) break;
                    slot = (slot + 1) & (HSIZE - 1);
                }
                if (inserted) {
                    g_visit[v] = L;
                    int pos = atomicAdd(&g_ctr.pair_tail, 1);
                    if (pos < PAIRMAX) g_pairs[pos] = make_uint2((unsigned)v, c);
                }
            }
        }
        grid_barrier(nblocks);
        int nh = g_ctr.pair_tail; if (nh > PAIRMAX) nh = PAIRMAX;
        grid_barrier(nblocks);
        lo = hi; hi = nh; L++;
    }
}

// ---------------- fold memberships: segment max of elev and x ----------------
__global__ void k_fold(const float* __restrict__ x, const void* batch, int C) {
    int is64 = g_is64;
    int np = g_ctr.pair_tail; if (np > PAIRMAX) np = PAIRMAX;
    int warp = (blockIdx.x * blockDim.x + threadIdx.x) >> 5;
    int lane = threadIdx.x & 31;
    int nw = (gridDim.x * blockDim.x) >> 5;
    for (int p = warp; p < np; p += nw) {
        uint2 pr = g_pairs[p];
        int v = (int)pr.x;
        int c = (int)pr.y;
        if (c >= PMAXP) continue;
        if (lane == 0) {
            int bt = (int)ld_idx(batch, v, is64);
            float elev = g_e[v] / g_bsum[bt];
            atomicMax(&g_maxelev[c], encf(elev));
        }
        const float* xr = x + (size_t)v * C;
        unsigned* mx = g_maxx + (size_t)c * C;
        for (int i = lane; i < C; i += 32) atomicMax(&mx[i], encf(xr[i]));
    }
}

// ---------------- per-batch softmax over clusters ----------------
__global__ void k_bstat1() {
    int P = g_nP; if (P > PMAXP) P = PMAXP;
    int p = blockIdx.x * blockDim.x + threadIdx.x;
    if (p >= P) return;
    float me = decf(g_maxelev[p]);
    atomicMax(&g_cbmax[g_cbv[p]], encf(me));
}
__global__ void k_bstat2() {
    int P = g_nP; if (P > PMAXP) P = PMAXP;
    int p = blockIdx.x * blockDim.x + threadIdx.x;
    if (p >= P) return;
    float me = decf(g_maxelev[p]);
    float ex = expf(me - decf(g_cbmax[g_cbv[p]]));
    g_exn[p] = ex;
    atomicAdd(&g_cbsum[g_cbv[p]], ex);
}

// ---------------- outputs ----------------
__global__ void k_out(float* __restrict__ out, int C) {
    int P = g_nP; if (P > PMAXP) P = PMAXP;
    int warp = (blockIdx.x * blockDim.x + threadIdx.x) >> 5;
    int lane = threadIdx.x & 31;
    int nw = (gridDim.x * blockDim.x) >> 5;
    for (int p = warp; p < P; p += nw) {
        float normed = g_exn[p] / g_cbsum[g_cbv[p]];
        const unsigned* mx = g_maxx + (size_t)p * C;
        float* orow = out + (size_t)p * C;
        for (int i = lane; i < C; i += 32) orow[i] = decf(mx[i]) * normed;
        if (lane == 0) out[(size_t)P * C + p] = (float)g_cbv[p];
    }
}
__global__ void k_elevout(float* __restrict__ out, const void* batch, int N, int C) {
    int is64 = g_is64;
    int P = g_nP; if (P > PMAXP) P = PMAXP;
    int n = blockIdx.x * blockDim.x + threadIdx.x;
    if (n >= N) return;
    int bt = (int)ld_idx(batch, n, is64);
    out[(size_t)P * (C + 1) + n] = g_e[n] / g_bsum[bt];
}

// ---------------- host launcher ----------------
extern "C" void kernel_launch(void* const* d_in, const int* in_sizes, int n_in,
                              void* d_out, int out_size) {
    const float* x  = (const float*)d_in[0];
    const void*  ei = d_in[1];
    const void*  bt = d_in[2];
    const float* W  = (const float*)d_in[3];
    const float* bb = (const float*)d_in[4];
    int N = in_sizes[2];
    int C = in_sizes[0] / (N > 0 ? N : 1);
    int E = in_sizes[1] / 2;
    float* out = (float*)d_out;

    // symbol addresses for memsets
    void *p_htab, *p_maxx, *p_maxelev, *p_notpeak, *p_outdeg, *p_visit;
    void *p_bmaxz, *p_bsum, *p_cbmax, *p_cbsum, *p_ctr;
    cudaGetSymbolAddress(&p_htab, g_htab);
    cudaGetSymbolAddress(&p_maxx, g_maxx);
    cudaGetSymbolAddress(&p_maxelev, g_maxelev);
    cudaGetSymbolAddress(&p_notpeak, g_notpeak);
    cudaGetSymbolAddress(&p_outdeg, g_outdeg);
    cudaGetSymbolAddress(&p_visit, g_visit);
    cudaGetSymbolAddress(&p_bmaxz, g_bmaxz);
    cudaGetSymbolAddress(&p_bsum, g_bsum);
    cudaGetSymbolAddress(&p_cbmax, g_cbmax);
    cudaGetSymbolAddress(&p_cbsum, g_cbsum);
    cudaGetSymbolAddress(&p_ctr, (const void*)&g_ctr);

    cudaStream_t s = 0;
    cudaMemsetAsync(p_htab, 0xFF, (size_t)HSIZE * 8, s);
    cudaMemsetAsync(p_maxx, 0x00, (size_t)PMAXP * CMAXC * 4, s);
    cudaMemsetAsync(p_maxelev, 0x00, (size_t)PMAXP * 4, s);
    cudaMemsetAsync(p_notpeak, 0x00, (size_t)N * 4, s);
    cudaMemsetAsync(p_outdeg, 0x00, (size_t)N * 4, s);
    cudaMemsetAsync(p_visit, 0x7F, (size_t)N * 4, s);
    cudaMemsetAsync(p_bmaxz, 0x00, BMAXB * 4, s);
    cudaMemsetAsync(p_bsum, 0x00, BMAXB * 4, s);
    cudaMemsetAsync(p_cbmax, 0x00, BMAXB * 4, s);
    cudaMemsetAsync(p_cbsum, 0x00, BMAXB * 4, s);
    cudaMemsetAsync(p_ctr, 0x00, sizeof(Ctr), s);

    int gN256 = (N + 255) / 256; if (gN256 < 1) gN256 = 1;
    int gE256 = (E + 255) / 256; if (gE256 < 1) gE256 = 1;
    int nb = (N + 1023) / 1024; if (nb < 1) nb = 1;

    k_sniff<<<1, 256, 0, s>>>(ei, E, N);

    { // z kernel: one warp per node
        long long threads = (long long)N * 32;
        int blocks = (int)((threads + 255) / 256); if (blocks < 1) blocks = 1;
        k_z<<<blocks, 256, 0, s>>>(x, W, bb, bt, N, C);
    }
    k_exp<<<gN256, 256, 0, s>>>(bt, N);
    k_edges<<<gE256, 256, 0, s>>>(ei, E);

    // peak rank scan
    int *a_notpeak, *a_peakrank, *a_bs, *a_nP, *a_outdeg2, *a_rowoff, *a_nEdesc;
    cudaGetSymbolAddress((void**)&a_notpeak, g_notpeak);
    cudaGetSymbolAddress((void**)&a_peakrank, g_peakrank);
    cudaGetSymbolAddress((void**)&a_bs, g_bs);
    cudaGetSymbolAddress((void**)&a_nP, g_nP);
    cudaGetSymbolAddress((void**)&a_outdeg2, g_outdeg);
    cudaGetSymbolAddress((void**)&a_rowoff, g_rowoff);
    cudaGetSymbolAddress((void**)&a_nEdesc, g_nEdesc);

    k_scan_partial<<<nb, 1024, 0, s>>>(a_notpeak, N, 1, a_peakrank, a_bs);
    k_scan_bsums<<<1, 1024, 0, s>>>(a_bs, nb, a_nP);
    k_scan_add<<<nb, 1024, 0, s>>>(a_peakrank, N, a_bs);

    // CSR offsets scan
    k_scan_partial<<<nb, 1024, 0, s>>>(a_outdeg2, N, 0, a_rowoff, a_bs);
    k_scan_bsums<<<1, 1024, 0, s>>>(a_bs, nb, a_nEdesc);
    k_scan_add<<<nb, 1024, 0, s>>>(a_rowoff, N, a_bs);

    k_peaklist<<<gN256, 256, 0, s>>>(bt, N);
    k_csrfill<<<gE256, 256, 0, s>>>(ei, E);

    // persistent BFS at exactly co-resident block count
    int smCount = 148, bpm = 4;
    cudaDeviceGetAttribute(&smCount, cudaDevAttrMultiProcessorCount, 0);
    cudaOccupancyMaxActiveBlocksPerMultiprocessor(&bpm, k_bfs, 256, 0);
    if (bpm < 1) bpm = 1;
    int nblocks = smCount * bpm;
    if (nblocks < 1) nblocks = 1;
    k_bfs<<<nblocks, 256, 0, s>>>(nblocks);

    k_fold<<<2048, 256, 0, s>>>(x, bt, C);
    k_bstat1<<<(PMAXP + 255) / 256, 256, 0, s>>>();
    k_bstat2<<<(PMAXP + 255) / 256, 256, 0, s>>>();
    k_out<<<1024, 256, 0, s>>>(out, C);
    k_elevout<<<gN256, 256, 0, s>>>(out, bt, N, C);
}

// round 2
// speedup vs baseline: 1.3913x; 1.3913x over previous
#include <cuda_runtime.h>
#include <cstdint>

#define NMAXN   131072
#define EMAXE   2200000
#define PMAXP   32768
#define CMAXC   256
#define BMAXB   64
#define HBITS   21
#define HSIZE   (1u << HBITS)
#define PAIRMAX 2097152
#define HEMPTY  0xFFFFFFFFFFFFFFFFull
#define BFS_BLOCKS 296
#define FIN_BLOCKS 128

__device__ float              g_z[NMAXN];
__device__ float              g_e[NMAXN];
__device__ int                g_notpeak[NMAXN];
__device__ int                g_visit[NMAXN];
__device__ int                g_outdeg[NMAXN];
__device__ int                g_rowoff[NMAXN + 1];
__device__ int                g_fillpos[NMAXN];
__device__ int                g_peakrank[NMAXN];
__device__ int                g_col[EMAXE];
__device__ uint2              g_desc[EMAXE];
__device__ uint2              g_pairs[PAIRMAX];
__device__ int                g_mlist[PAIRMAX];
__device__ unsigned long long g_htab[HSIZE];
__device__ float              g_poolmax[(size_t)PMAXP * CMAXC];
__device__ float              g_maxelevF[PMAXP];
__device__ int                g_cbv[PMAXP];
__device__ float              g_exn[PMAXP];
__device__ int                g_ccount[PMAXP];
__device__ int                g_cc2[PMAXP];
__device__ int                g_rowP[PMAXP + 1];
__device__ unsigned           g_bmaxz[BMAXB];
__device__ float              g_bsum[BMAXB];
__device__ unsigned           g_cbmax[BMAXB];
__device__ float              g_cbsum[BMAXB];
__device__ int                g_bsA[1024];
__device__ int                g_bsB[1024];
__device__ int                g_nP;
__device__ int                g_is64;

struct Ctr { int pair_tail; int desc_tail; int bar_count; int bar_gen; int fbar_count; int fbar_gen; };
__device__ Ctr g_ctr;

// ---------------- helpers ----------------
__device__ __forceinline__ unsigned encf(float f) {
    unsigned u = __float_as_uint(f);
    return (u & 0x80000000u) ? ~u : (u | 0x80000000u);
}
__device__ __forceinline__ float decf(unsigned u) {
    return __uint_as_float((u & 0x80000000u) ? (u ^ 0x80000000u) : ~u);
}
__device__ __forceinline__ long long ld_idx(const void* p, long long i, int is64) {
    if (is64) return ((const long long*)p)[i];
    return (long long)((const int*)p)[i];
}
__device__ __forceinline__ void gbar(int nblocks, int* cnt, volatile int* gen) {
    __syncthreads();
    if (threadIdx.x == 0) {
        __threadfence();
        int g = *gen;
        if (atomicAdd(cnt, 1) == nblocks - 1) {
            *cnt = 0;
            __threadfence();
            *gen = g + 1;
        } else {
            while (*gen == g) { __nanosleep(64); }
        }
        __threadfence();
    }
    __syncthreads();
}

// ---------------- init: all scratch clears + dtype sniff, one launch ----------------
__global__ void k_init(const void* ei, int E, int N) {
    size_t stride = (size_t)gridDim.x * blockDim.x;
    size_t t = (size_t)blockIdx.x * blockDim.x + threadIdx.x;
    for (size_t i = t; i < HSIZE; i += stride) g_htab[i] = HEMPTY;
    for (size_t i = t; i < (size_t)N; i += stride) {
        g_visit[i] = 0x7FFFFFFF; g_notpeak[i] = 0; g_outdeg[i] = 0; g_fillpos[i] = 0;
    }
    for (size_t i = t; i < PMAXP; i += stride) { g_ccount[i] = 0; g_cc2[i] = 0; }
    if (t < BMAXB) { g_bmaxz[t] = 0u; g_bsum[t] = 0.f; g_cbmax[t] = 0u; g_cbsum[t] = 0.f; }
    if (t == 0) {
        g_ctr.pair_tail = 0; g_ctr.desc_tail = 0;
        g_ctr.bar_count = 0; g_ctr.bar_gen = 0;
        g_ctr.fbar_count = 0; g_ctr.fbar_gen = 0;
    }
    if (blockIdx.x == 0) {
        __shared__ int ok;
        if (threadIdx.x == 0) ok = 1;
        __syncthreads();
        int ncheck = E < 512 ? E : 512;
        for (int i = threadIdx.x; i < ncheck; i += blockDim.x) {
            long long v = ((const long long*)ei)[i];
            if (v < 0 || v >= (long long)N) atomicExch(&ok, 0);
        }
        __syncthreads();
        if (threadIdx.x == 0) g_is64 = ok;
    }
}

// ---------------- z = x @ W^T + b (fp32 partials, fp64 tree reduce) ----------------
__global__ void k_z(const float* __restrict__ x, const float* __restrict__ W,
                    const float* __restrict__ bb, const void* batch, int N, int C) {
    __shared__ unsigned s_bmax[BMAXB];
    if (threadIdx.x < BMAXB) s_bmax[threadIdx.x] = 0u;
    __syncthreads();
    int is64 = g_is64;
    int gw = (blockIdx.x * blockDim.x + threadIdx.x) >> 5;
    int lane = threadIdx.x & 31;
    int nw = (gridDim.x * blockDim.x) >> 5;
    int C4 = C >> 2;
    for (int n = gw; n < N; n += nw) {
        const float4* xr = (const float4*)(x + (size_t)n * C);
        const float4* wr = (const float4*)W;
        float acc = 0.f;
        for (int i = lane; i < C4; i += 32) {
            float4 a = xr[i], w = wr[i];
            acc += a.x * w.x + a.y * w.y + a.z * w.z + a.w * w.w;
        }
        for (int i = C4 * 4 + lane; i < C; i += 32) acc += x[(size_t)n * C + i] * W[i];
        double d = (double)acc;
        #pragma unroll
        for (int o = 16; o; o >>= 1) d += __shfl_down_sync(0xffffffffu, d, o);
        if (lane == 0) {
            float zf = (float)d + bb[0];
            g_z[n] = zf;
            int bt = (int)ld_idx(batch, n, is64);
            if (bt >= 0 && bt < BMAXB) atomicMax(&s_bmax[bt], encf(zf));
        }
    }
    __syncthreads();
    if (threadIdx.x < BMAXB && s_bmax[threadIdx.x] != 0u)
        atomicMax(&g_bmaxz[threadIdx.x], s_bmax[threadIdx.x]);
}

// ---------------- fused: e=exp(z-m), batch sums; peak flags + descending edge list ----------------
__global__ void k_expedges(const void* ei, const void* batch, int N, int E) {
    __shared__ float ssum[BMAXB];
    if (threadIdx.x < BMAXB) ssum[threadIdx.x] = 0.f;
    __syncthreads();
    int is64 = g_is64;
    int stride = gridDim.x * blockDim.x;
    for (int n = blockIdx.x * blockDim.x + threadIdx.x; n < N; n += stride) {
        int bt = (int)ld_idx(batch, n, is64);
        float ev = expf(g_z[n] - decf(g_bmaxz[bt]));
        g_e[n] = ev;
        atomicAdd(&ssum[bt], ev);
    }
    __syncthreads();
    if (threadIdx.x < BMAXB && ssum[threadIdx.x] != 0.f)
        atomicAdd(&g_bsum[threadIdx.x], ssum[threadIdx.x]);
    for (int e = blockIdx.x * blockDim.x + threadIdx.x; e < E; e += stride) {
        int ls = (int)ld_idx(ei, e, is64);
        int ld = (int)ld_idx(ei, (long long)E + e, is64);
        float zs = g_z[ls], zd = g_z[ld];
        if (zd < zs) g_notpeak[ld] = 1;
        bool desc = (zd <= zs);
        unsigned m = __ballot_sync(__activemask(), desc);
        if (desc) {
            int lane = threadIdx.x & 31;
            int leader = __ffs(m) - 1;
            int base = 0;
            if (lane == leader) base = atomicAdd(&g_ctr.desc_tail, __popc(m));
            base = __shfl_sync(m, base, leader);
            int pos = base + __popc(m & ((1u << lane) - 1));
            if (pos < EMAXE) g_desc[pos] = make_uint2((unsigned)ls, (unsigned)ld);
            atomicAdd(&g_outdeg[ls], 1);
        }
    }
}

// ---------------- dual exclusive scans (peakrank over !notpeak, rowoff over outdeg) ----------------
__global__ void k_scanA(int n) {
    __shared__ int sa[1024], sb[1024];
    int gid = blockIdx.x * 1024 + threadIdx.x;
    int va = 0, vb = 0;
    if (gid < n) { va = (g_notpeak[gid] == 0) ? 1 : 0; vb = g_outdeg[gid]; }
    sa[threadIdx.x] = va; sb[threadIdx.x] = vb;
    __syncthreads();
    for (int off = 1; off < 1024; off <<= 1) {
        int ta = 0, tb = 0;
        if (threadIdx.x >= off) { ta = sa[threadIdx.x - off]; tb = sb[threadIdx.x - off]; }
        __syncthreads();
        if (threadIdx.x >= off) { sa[threadIdx.x] += ta; sb[threadIdx.x] += tb; }
        __syncthreads();
    }
    if (gid < n) { g_peakrank[gid] = sa[threadIdx.x] - va; g_rowoff[gid] = sb[threadIdx.x] - vb; }
    if (threadIdx.x == 1023) { g_bsA[blockIdx.x] = sa[1023]; g_bsB[blockIdx.x] = sb[1023]; }
}
__global__ void k_scanB(int nb) {
    __shared__ int sa[1024], sb[1024];
    int va = (threadIdx.x < nb) ? g_bsA[threadIdx.x] : 0;
    int vb = (threadIdx.x < nb) ? g_bsB[threadIdx.x] : 0;
    sa[threadIdx.x] = va; sb[threadIdx.x] = vb;
    __syncthreads();
    for (int off = 1; off < 1024; off <<= 1) {
        int ta = 0, tb = 0;
        if (threadIdx.x >= off) { ta = sa[threadIdx.x - off]; tb = sb[threadIdx.x - off]; }
        __syncthreads();
        if (threadIdx.x >= off) { sa[threadIdx.x] += ta; sb[threadIdx.x] += tb; }
        __syncthreads();
    }
    if (threadIdx.x < nb) { g_bsA[threadIdx.x] = sa[threadIdx.x] - va; g_bsB[threadIdx.x] = sb[threadIdx.x] - vb; }
    if (threadIdx.x == 1023) g_nP = sa[1023];
}
__global__ void k_scanC(int n) {
    int gid = blockIdx.x * 1024 + threadIdx.x;
    if (gid < n) { g_peakrank[gid] += g_bsA[blockIdx.x]; g_rowoff[gid] += g_bsB[blockIdx.x]; }
}

// ---------------- peak list + CSR column scatter (fused) ----------------
__global__ void k_plc(const void* batch, int N) {
    int is64 = g_is64;
    int stride = gridDim.x * blockDim.x;
    int t0 = blockIdx.x * blockDim.x + threadIdx.x;
    if (t0 == 0) {
        int P = g_nP; if (P > PMAXP) P = PMAXP;
        g_ctr.pair_tail = P;
        g_rowoff[N] = g_ctr.desc_tail;
    }
    for (int n = t0; n < N; n += stride) {
        if (!g_notpeak[n]) {
            int r = g_peakrank[n];
            g_visit[n] = 0;
            if (r < PMAXP) {
                g_cbv[r] = (int)ld_idx(batch, n, is64);
                g_pairs[r] = make_uint2((unsigned)n, (unsigned)r);
                g_ccount[r] = 1;
            }
        }
    }
    int D = g_ctr.desc_tail; if (D > EMAXE) D = EMAXE;
    for (int e = t0; e < D; e += stride) {
        uint2 ed = g_desc[e];
        int ls = (int)ed.x;
        int pos = g_rowoff[ls] + atomicAdd(&g_fillpos[ls], 1);
        if (pos < EMAXE) g_col[pos] = (int)ed.y;
    }
}

// ---------------- persistent level-synchronous BFS ----------------
__global__ void __launch_bounds__(256) k_bfs() {
    int lo = 0;
    int hi = g_nP; if (hi > PMAXP) hi = PMAXP;
    int L = 1;
    while (hi > lo && L < 200000) {
        int stride = BFS_BLOCKS * 256;
        for (int i = lo + blockIdx.x * 256 + (int)threadIdx.x; i < hi; i += stride) {
            uint2 pr = g_pairs[i];
            int u = (int)pr.x;
            unsigned c = pr.y;
            int beg = g_rowoff[u], end = g_rowoff[u + 1];
            for (int j = beg; j < end; j++) {
                int v = g_col[j];
                if (g_visit[v] < L) continue;
                unsigned long long key = ((unsigned long long)(unsigned)v << 32) | c;
                unsigned long long h = key * 0x9E3779B97F4A7C15ull;
                h ^= h >> 33; h *= 0xff51afd7ed558ccdull; h ^= h >> 33;
                unsigned slot = (unsigned)h & (HSIZE - 1);
                bool inserted = false;
                while (true) {
                    unsigned long long prev = atomicCAS(&g_htab[slot], HEMPTY, key);
                    if (prev == HEMPTY) { inserted = true; break; }
                    if (prev == key) break;
                    slot = (slot + 1) & (HSIZE - 1);
                }
                if (inserted) {
                    g_visit[v] = L;
                    if (c < PMAXP) atomicAdd(&g_ccount[c], 1);
                    int pos = atomicAdd(&g_ctr.pair_tail, 1);
                    if (pos < PAIRMAX) g_pairs[pos] = make_uint2((unsigned)v, c);
                }
            }
        }
        gbar(BFS_BLOCKS, &g_ctr.bar_count, &g_ctr.bar_gen);
        int nh = g_ctr.pair_tail; if (nh > PAIRMAX) nh = PAIRMAX;
        gbar(BFS_BLOCKS, &g_ctr.bar_count, &g_ctr.bar_gen);
        lo = hi; hi = nh; L++;
    }
}

// ---------------- single-block exclusive scan over cluster counts ----------------
__global__ void k_scanP() {
    __shared__ int sh[1024];
    __shared__ int carry;
    if (threadIdx.x == 0) carry = 0;
    __syncthreads();
    for (int base = 0; base < PMAXP; base += 1024) {
        int v = g_ccount[base + threadIdx.x];
        sh[threadIdx.x] = v;
        __syncthreads();
        for (int off = 1; off < 1024; off <<= 1) {
            int t = 0;
            if (threadIdx.x >= off) t = sh[threadIdx.x - off];
            __syncthreads();
            if (threadIdx.x >= off) sh[threadIdx.x] += t;
            __syncthreads();
        }
        g_rowP[base + threadIdx.x] = carry + sh[threadIdx.x] - v;
        __syncthreads();
        if (threadIdx.x == 1023) carry += sh[1023];
        __syncthreads();
    }
    if (threadIdx.x == 0) g_rowP[PMAXP] = carry;
}

// ---------------- scatter pairs into per-cluster member lists ----------------
__global__ void k_scatter() {
    int np = g_ctr.pair_tail; if (np > PAIRMAX) np = PAIRMAX;
    int stride = gridDim.x * blockDim.x;
    for (int i = blockIdx.x * blockDim.x + threadIdx.x; i < np; i += stride) {
        uint2 pr = g_pairs[i];
        unsigned c = pr.y;
        if (c >= PMAXP) continue;
        int pos = g_rowP[c] + atomicAdd(&g_cc2[c], 1);
        if (pos < PAIRMAX) g_mlist[pos] = (int)pr.x;
    }
}

// ---------------- gather: per-cluster max of elev and x (no atomics) ----------------
__global__ void __launch_bounds__(256) k_gather(const float* __restrict__ x,
                                                const void* batch, int C) {
    int is64 = g_is64;
    int P = g_nP; if (P > PMAXP) P = PMAXP;
    __shared__ float sred[256];
    __shared__ int smem_m[256];
    for (int p = blockIdx.x; p < P; p += gridDim.x) {
        int beg = g_rowP[p], end = g_rowP[p + 1];
        // max elev over members
        float em = -1e30f;
        for (int m = beg + (int)threadIdx.x; m < end; m += 256) {
            int v = g_mlist[m];
            int bt = (int)ld_idx(batch, v, is64);
            em = fmaxf(em, g_e[v] / g_bsum[bt]);
        }
        sred[threadIdx.x] = em;
        __syncthreads();
        for (int off = 128; off; off >>= 1) {
            if (threadIdx.x < off) sred[threadIdx.x] = fmaxf(sred[threadIdx.x], sred[threadIdx.x + off]);
            __syncthreads();
        }
        if (threadIdx.x == 0) g_maxelevF[p] = sred[0];
        // channel max: member ids staged in shared, thread = channel
        float vm = -1e30f;
        for (int mb = beg; mb < end; mb += 256) {
            int cnt = end - mb; if (cnt > 256) cnt = 256;
            __syncthreads();
            if ((int)threadIdx.x < cnt) smem_m[threadIdx.x] = g_mlist[mb + threadIdx.x];
            __syncthreads();
            if ((int)threadIdx.x < C) {
                for (int j = 0; j < cnt; j++)
                    vm = fmaxf(vm, x[(size_t)smem_m[j] * C + threadIdx.x]);
            }
        }
        if ((int)threadIdx.x < C) g_poolmax[(size_t)p * C + threadIdx.x] = vm;
        // fallback for C > 256 (not expected)
        for (int ch = 256 + (int)threadIdx.x; ch < C; ch += 256) {
            float v2 = -1e30f;
            for (int m = beg; m < end; m++)
                v2 = fmaxf(v2, x[(size_t)g_mlist[m] * C + ch]);
            g_poolmax[(size_t)p * C + ch] = v2;
        }
        __syncthreads();
    }
}

// ---------------- epilogue: batch softmax over clusters + all outputs ----------------
__global__ void __launch_bounds__(256) k_final(float* __restrict__ out,
                                               const void* batch, int N, int C) {
    int is64 = g_is64;
    int P = g_nP; if (P > PMAXP) P = PMAXP;
    __shared__ unsigned smax[BMAXB];
    __shared__ float ssum[BMAXB];
    // phase 1: per-batch max of cluster maxelev
    if (threadIdx.x < BMAXB) smax[threadIdx.x] = 0u;
    __syncthreads();
    for (int p = blockIdx.x * 256 + (int)threadIdx.x; p < P; p += FIN_BLOCKS * 256)
        atomicMax(&smax[g_cbv[p]], encf(g_maxelevF[p]));
    __syncthreads();
    if (threadIdx.x < BMAXB && smax[threadIdx.x] != 0u)
        atomicMax(&g_cbmax[threadIdx.x], smax[threadIdx.x]);
    gbar(FIN_BLOCKS, &g_ctr.fbar_count, &g_ctr.fbar_gen);
    // phase 2: exp + per-batch sum
    if (threadIdx.x < BMAXB) ssum[threadIdx.x] = 0.f;
    __syncthreads();
    for (int p = blockIdx.x * 256 + (int)threadIdx.x; p < P; p += FIN_BLOCKS * 256) {
        float ex = expf(g_maxelevF[p] - decf(g_cbmax[g_cbv[p]]));
        g_exn[p] = ex;
        atomicAdd(&ssum[g_cbv[p]], ex);
    }
    __syncthreads();
    if (threadIdx.x < BMAXB && ssum[threadIdx.x] != 0.f)
        atomicAdd(&g_cbsum[threadIdx.x], ssum[threadIdx.x]);
    gbar(FIN_BLOCKS, &g_ctr.fbar_count, &g_ctr.fbar_gen);
    // phase 3: outputs
    int warp = (blockIdx.x * 256 + (int)threadIdx.x) >> 5;
    int lane = threadIdx.x & 31;
    int nw = FIN_BLOCKS * 8;
    for (int p = warp; p < P; p += nw) {
        float normed = g_exn[p] / g_cbsum[g_cbv[p]];
        const float* mx = g_poolmax + (size_t)p * C;
        float* orow = out + (size_t)p * C;
        for (int i = lane; i < C; i += 32) orow[i] = mx[i] * normed;
        if (lane == 0) out[(size_t)P * C + p] = (float)g_cbv[p];
    }
    for (int n = blockIdx.x * 256 + (int)threadIdx.x; n < N; n += FIN_BLOCKS * 256) {
        int bt = (int)ld_idx(batch, n, is64);
        out[(size_t)P * (C + 1) + n] = g_e[n] / g_bsum[bt];
    }
}

// ---------------- host launcher ----------------
extern "C" void kernel_launch(void* const* d_in, const int* in_sizes, int n_in,
                              void* d_out, int out_size) {
    const float* x  = (const float*)d_in[0];
    const void*  ei = d_in[1];
    const void*  bt = d_in[2];
    const float* W  = (const float*)d_in[3];
    const float* bb = (const float*)d_in[4];
    int N = in_sizes[2];
    int C = in_sizes[0] / (N > 0 ? N : 1);
    int E = in_sizes[1] / 2;
    float* out = (float*)d_out;
    cudaStream_t s = 0;

    int gNE = ((N > E ? N : E) + 255) / 256; if (gNE < 1) gNE = 1;
    int nb = (N + 1023) / 1024; if (nb < 1) nb = 1;

    k_init<<<2048, 256, 0, s>>>(ei, E, N);
    {
        long long threads = (long long)N * 32;
        int blocks = (int)((threads + 255) / 256); if (blocks < 1) blocks = 1;
        k_z<<<blocks, 256, 0, s>>>(x, W, bb, bt, N, C);
    }
    k_expedges<<<gNE, 256, 0, s>>>(ei, bt, N, E);
    k_scanA<<<nb, 1024, 0, s>>>(N);
    k_scanB<<<1, 1024, 0, s>>>(nb);
    k_scanC<<<nb, 1024, 0, s>>>(N);
    k_plc<<<4096, 256, 0, s>>>(bt, N);
    k_bfs<<<BFS_BLOCKS, 256, 0, s>>>();
    k_scanP<<<1, 1024, 0, s>>>();
    k_scatter<<<2048, 256, 0, s>>>();
    k_gather<<<2048, 256, 0, s>>>(x, bt, C);
    k_final<<<FIN_BLOCKS, 256, 0, s>>>(out, bt, N, C);
}

// round 4
// speedup vs baseline: 1.5375x; 1.1051x over previous
#include <cuda_runtime.h>
#include <cstdint>

#define NMAXN   131072
#define EMAXE   2200000
#define PMAXP   32768
#define CMAXC   256
#define BMAXB   64
#define HBITS   21
#define HSIZE   (1u << HBITS)
#define PAIRMAX 2097152
#define HEMPTY  0xFFFFFFFFFFFFFFFFull
#define VUNSET  0xFFFFFFFFFFFFFFFFull
#define MAXPROBE 128

__device__ float              g_z[NMAXN];
__device__ float              g_e[NMAXN];
__device__ int                g_notpeak[NMAXN];
__device__ unsigned long long g_visitcl[NMAXN];
__device__ int                g_outdeg[NMAXN];
__device__ int                g_rowoff[NMAXN + 1];
__device__ int                g_fillpos[NMAXN];
__device__ int                g_peakrank[NMAXN];
__device__ int                g_col[EMAXE];
__device__ uint2              g_desc[EMAXE];
__device__ uint2              g_pairs[PAIRMAX];
__device__ int                g_mlist[PAIRMAX];
__device__ unsigned long long g_htab[HSIZE];
__device__ float              g_poolmax[(size_t)PMAXP * CMAXC];
__device__ float              g_maxelevF[PMAXP];
__device__ int                g_cbv[PMAXP];
__device__ float              g_exn[PMAXP];
__device__ int                g_ccount[PMAXP];
__device__ int                g_cc2[PMAXP];
__device__ int                g_rowP[PMAXP + 1];
__device__ unsigned           g_bmaxz[BMAXB];
__device__ float              g_bsum[BMAXB];
__device__ unsigned           g_cbmax[BMAXB];
__device__ float              g_cbsum[BMAXB];
__device__ int                g_bsA[1024];
__device__ int                g_bsB[1024];
__device__ int                g_nP;
__device__ int                g_is64;
__device__ int                g_pair_tail;
__device__ int                g_desc_tail;

struct Bar { int cnt; int gen; int snap; };
__device__ Bar g_barA;
__device__ Bar g_barB;

// ---------------- helpers ----------------
__device__ __forceinline__ unsigned encf(float f) {
    unsigned u = __float_as_uint(f);
    return (u & 0x80000000u) ? ~u : (u | 0x80000000u);
}
__device__ __forceinline__ float decf(unsigned u) {
    return __uint_as_float((u & 0x80000000u) ? (u ^ 0x80000000u) : ~u);
}
__device__ __forceinline__ long long ld_idx(const void* p, long long i, int is64) {
    if (is64) return ((const long long*)p)[i];
    return (long long)((const int*)p)[i];
}
__device__ __forceinline__ void gbar(Bar* b) {
    __syncthreads();
    if (threadIdx.x == 0) {
        __threadfence();
        volatile int* vg = &b->gen;
        int g = *vg;
        if (atomicAdd(&b->cnt, 1) == (int)gridDim.x - 1) {
            b->cnt = 0;
            __threadfence();
            atomicExch(&b->gen, g + 1);
        } else {
            int it = 0;
            while (*vg == g) { if (++it > 4096) { __nanosleep(128); it = 2048; } }
        }
        __threadfence();
    }
    __syncthreads();
}
// barrier + snapshot of g_pair_tail taken by the releasing block
__device__ __forceinline__ int gbar_snap(Bar* b) {
    __shared__ int s_hi;
    __syncthreads();
    if (threadIdx.x == 0) {
        __threadfence();
        volatile int* vg = &b->gen;
        volatile int* vs = &b->snap;
        int g = *vg;
        if (atomicAdd(&b->cnt, 1) == (int)gridDim.x - 1) {
            int nt = g_pair_tail; if (nt > PAIRMAX) nt = PAIRMAX;
            *vs = nt;
            b->cnt = 0;
            __threadfence();
            atomicExch(&b->gen, g + 1);
            s_hi = nt;
        } else {
            int it = 0;
            while (*vg == g) { if (++it > 4096) { __nanosleep(128); it = 2048; } }
            __threadfence();
            s_hi = *vs;
        }
        __threadfence();
    }
    __syncthreads();
    return s_hi;
}

// ---------------- L1: init clears + sniff + z + per-batch max ----------------
__global__ void k_initz(const float* __restrict__ x, const float* __restrict__ W,
                        const float* __restrict__ bb, const void* batch,
                        const void* ei, int N, int C, int E) {
    __shared__ unsigned s_bmax[BMAXB];
    __shared__ int s_is64;
    int tid = threadIdx.x;
    if (tid < 32) {
        int nch = E < 8 ? E : 8;
        bool bad = false;
        if (tid < nch) {
            long long v = ((const long long*)ei)[tid];
            bad = (v < 0 || v >= (long long)N);
        }
        unsigned m = __ballot_sync(0xffffffffu, bad);
        if (tid == 0) s_is64 = (m == 0) ? 1 : 0;
    }
    if (tid < BMAXB) s_bmax[tid] = 0u;
    __syncthreads();
    int is64 = s_is64;
    size_t t = (size_t)blockIdx.x * blockDim.x + tid;
    size_t stride = (size_t)gridDim.x * blockDim.x;
    for (size_t i = t; i < HSIZE; i += stride) g_htab[i] = HEMPTY;
    for (size_t i = t; i < (size_t)N; i += stride) {
        g_visitcl[i] = VUNSET; g_notpeak[i] = 0; g_outdeg[i] = 0; g_fillpos[i] = 0;
    }
    for (size_t i = t; i < PMAXP; i += stride) { g_ccount[i] = 0; g_cc2[i] = 0; }
    if (t < BMAXB) { g_bmaxz[t] = 0u; g_bsum[t] = 0.f; g_cbmax[t] = 0u; g_cbsum[t] = 0.f; }
    if (t == 0) {
        g_pair_tail = 0; g_desc_tail = 0;
        g_barA.cnt = 0; g_barA.gen = 0; g_barA.snap = 0;
        g_barB.cnt = 0; g_barB.gen = 0; g_barB.snap = 0;
        g_is64 = is64;
    }
    // z = x @ W^T + b, warp per node
    int gw = (int)(((size_t)blockIdx.x * blockDim.x + tid) >> 5);
    int lane = tid & 31;
    int nw = (int)(((size_t)gridDim.x * blockDim.x) >> 5);
    int C4 = (C % 4 == 0) ? (C >> 2) : 0;
    for (int n = gw; n < N; n += nw) {
        float acc = 0.f;
        if (C4) {
            const float4* xr = (const float4*)(x + (size_t)n * C);
            const float4* wr = (const float4*)W;
            for (int i = lane; i < C4; i += 32) {
                float4 a = xr[i], w = wr[i];
                acc += a.x * w.x + a.y * w.y + a.z * w.z + a.w * w.w;
            }
        } else {
            for (int i = lane; i < C; i += 32) acc += x[(size_t)n * C + i] * W[i];
        }
        double d = (double)acc;
        #pragma unroll
        for (int o = 16; o; o >>= 1) d += __shfl_down_sync(0xffffffffu, d, o);
        if (lane == 0) {
            float zf = (float)d + bb[0];
            g_z[n] = zf;
            long long bt = ld_idx(batch, n, is64);
            if (bt >= 0 && bt < BMAXB) atomicMax(&s_bmax[bt], encf(zf));
        }
    }
    __syncthreads();
    if (tid < BMAXB && s_bmax[tid] != 0u) atomicMax(&g_bmaxz[tid], s_bmax[tid]);
}

// ---------------- L2: exp + batch sums + peak flags + descending edge list ----------------
__global__ void k_ee(const void* ei, const void* batch, int N, int E) {
    __shared__ float ssum[BMAXB];
    int tid = threadIdx.x;
    if (tid < BMAXB) ssum[tid] = 0.f;
    __syncthreads();
    int is64 = g_is64;
    int stride = gridDim.x * blockDim.x;
    for (int n = blockIdx.x * blockDim.x + tid; n < N; n += stride) {
        long long bt = ld_idx(batch, n, is64);
        float ev = expf(g_z[n] - decf(g_bmaxz[bt]));
        g_e[n] = ev;
        atomicAdd(&ssum[bt], ev);
    }
    __syncthreads();
    if (tid < BMAXB && ssum[tid] != 0.f) atomicAdd(&g_bsum[tid], ssum[tid]);
    for (int e = blockIdx.x * blockDim.x + tid; e < E; e += stride) {
        int ls = (int)ld_idx(ei, e, is64);
        int ld = (int)ld_idx(ei, (long long)E + e, is64);
        float zs = g_z[ls], zd = g_z[ld];
        if (zd < zs) g_notpeak[ld] = 1;
        bool desc = (zd <= zs);
        unsigned m = __ballot_sync(__activemask(), desc);
        if (desc) {
            int lane = tid & 31;
            int leader = __ffs(m) - 1;
            int base = 0;
            if (lane == leader) base = atomicAdd(&g_desc_tail, __popc(m));
            base = __shfl_sync(m, base, leader);
            int pos = base + __popc(m & ((1u << lane) - 1));
            if (pos < EMAXE) g_desc[pos] = make_uint2((unsigned)ls, (unsigned)ld);
            atomicAdd(&g_outdeg[ls], 1);
        }
    }
}

// ---------------- L3: scans + peak init + CSR fill + BFS + cluster scan + scatter ----------------
__global__ void __launch_bounds__(256) k_bfsmega(const void* batch, int N) {
    __shared__ int sa[256], sb[256];
    __shared__ int s_cA, s_cB;
    int tid = threadIdx.x;
    int is64 = g_is64;
    int NCH = (N + 255) >> 8;
    // S1: per-chunk dual scan (peak indicator, outdeg)
    for (int ch = blockIdx.x; ch < NCH; ch += gridDim.x) {
        int gid = (ch << 8) + tid;
        int va = 0, vb = 0;
        if (gid < N) { va = g_notpeak[gid] ? 0 : 1; vb = g_outdeg[gid]; }
        sa[tid] = va; sb[tid] = vb; __syncthreads();
        for (int off = 1; off < 256; off <<= 1) {
            int ta = 0, tb = 0;
            if (tid >= off) { ta = sa[tid - off]; tb = sb[tid - off]; }
            __syncthreads();
            if (tid >= off) { sa[tid] += ta; sb[tid] += tb; }
            __syncthreads();
        }
        if (gid < N) { g_peakrank[gid] = sa[tid] - va; g_rowoff[gid] = sb[tid] - vb; }
        if (tid == 255) { g_bsA[ch] = sa[255]; g_bsB[ch] = sb[255]; }
        __syncthreads();
    }
    gbar(&g_barA);
    // S2: block 0 scans chunk sums
    if (blockIdx.x == 0) {
        if (tid == 0) { s_cA = 0; s_cB = 0; }
        __syncthreads();
        for (int base = 0; base < NCH; base += 256) {
            int i = base + tid;
            int va = (i < NCH) ? g_bsA[i] : 0;
            int vb = (i < NCH) ? g_bsB[i] : 0;
            sa[tid] = va; sb[tid] = vb; __syncthreads();
            for (int off = 1; off < 256; off <<= 1) {
                int ta = 0, tb = 0;
                if (tid >= off) { ta = sa[tid - off]; tb = sb[tid - off]; }
                __syncthreads();
                if (tid >= off) { sa[tid] += ta; sb[tid] += tb; }
                __syncthreads();
            }
            if (i < NCH) { g_bsA[i] = s_cA + sa[tid] - va; g_bsB[i] = s_cB + sb[tid] - vb; }
            __syncthreads();
            if (tid == 0) { s_cA += sa[255]; s_cB += sb[255]; }
            __syncthreads();
        }
        if (tid == 0) {
            g_nP = s_cA;
            g_rowoff[N] = s_cB;
            g_pair_tail = (s_cA > PMAXP) ? PMAXP : s_cA;
        }
    }
    gbar(&g_barA);
    int stride = gridDim.x * 256;
    // S3: finalize offsets + peak init
    for (int n = blockIdx.x * 256 + tid; n < N; n += stride) {
        int pr = g_peakrank[n] + g_bsA[n >> 8];
        int ro = g_rowoff[n] + g_bsB[n >> 8];
        g_rowoff[n] = ro;
        if (!g_notpeak[n] && pr < PMAXP) {
            long long bt = ld_idx(batch, n, is64);
            g_cbv[pr] = (int)bt;
            g_pairs[pr] = make_uint2((unsigned)n, (unsigned)pr);
            g_ccount[pr] = 1;
            g_visitcl[n] = (unsigned long long)(unsigned)pr;  // level 0
        }
    }
    gbar(&g_barA);
    // S4: CSR column fill
    {
        int D = g_desc_tail; if (D > EMAXE) D = EMAXE;
        for (int e = blockIdx.x * 256 + tid; e < D; e += stride) {
            uint2 ed = g_desc[e];
            int ls = (int)ed.x;
            int pos = g_rowoff[ls] + atomicAdd(&g_fillpos[ls], 1);
            if (pos < EMAXE) g_col[pos] = (int)ed.y;
        }
    }
    gbar(&g_barA);
    // BFS levels (single barrier per level)
    int P = g_nP; if (P > PMAXP) P = PMAXP;
    int lo = 0, hi = P, L = 1;
    while (hi > lo && L < 100000) {
        for (int i = lo + blockIdx.x * 256 + tid; i < hi; i += stride) {
            uint2 pr = g_pairs[i];
            int u = (int)pr.x;
            unsigned c = pr.y;
            int beg = g_rowoff[u], end = g_rowoff[u + 1];
            unsigned long long mine = ((unsigned long long)(unsigned)L << 32) | c;
            for (int j = beg; j < end; j++) {
                int v = g_col[j];
                unsigned long long cur = g_visitcl[v];
                while (true) {
                    unsigned curL = (unsigned)(cur >> 32);
                    if (curL < (unsigned)L) break;            // claimed earlier level
                    if (curL == (unsigned)L) {
                        if ((unsigned)cur == c) break;        // duplicate same cluster
                        // same-level tie with different cluster -> bounded hash dedup
                        unsigned long long key = ((unsigned long long)(unsigned)v << 32) | c;
                        unsigned long long h = key * 0x9E3779B97F4A7C15ull;
                        h ^= h >> 29; h *= 0xBF58476D1CE4E5B9ull; h ^= h >> 32;
                        unsigned slot = (unsigned)h & (HSIZE - 1);
                        bool ins = false;
                        for (int pb = 0; pb < MAXPROBE; pb++) {
                            unsigned long long prev = atomicCAS(&g_htab[slot], HEMPTY, key);
                            if (prev == HEMPTY) { ins = true; break; }
                            if (prev == key) break;
                            slot = (slot + 1) & (HSIZE - 1);
                            if (pb == MAXPROBE - 1) ins = true;  // fallback: accept (dup is harmless for max)
                        }
                        if (ins) {
                            atomicAdd(&g_ccount[c], 1);
                            int pos = atomicAdd(&g_pair_tail, 1);
                            if (pos < PAIRMAX) g_pairs[pos] = make_uint2((unsigned)v, c);
                        }
                        break;
                    }
                    unsigned long long prev = atomicCAS(&g_visitcl[v], cur, mine);
                    if (prev == cur) {
                        atomicAdd(&g_ccount[c], 1);
                        int pos = atomicAdd(&g_pair_tail, 1);
                        if (pos < PAIRMAX) g_pairs[pos] = make_uint2((unsigned)v, c);
                        break;
                    }
                    cur = prev;
                }
            }
        }
        int nh = gbar_snap(&g_barA);
        lo = hi; hi = nh; L++;
    }
    // scanP: exclusive scan over cluster counts
    int NPCH = (P + 255) >> 8;
    for (int ch = blockIdx.x; ch < NPCH; ch += gridDim.x) {
        int gid = (ch << 8) + tid;
        int v = (gid < P) ? g_ccount[gid] : 0;
        sa[tid] = v; __syncthreads();
        for (int off = 1; off < 256; off <<= 1) {
            int t2 = 0;
            if (tid >= off) t2 = sa[tid - off];
            __syncthreads();
            if (tid >= off) sa[tid] += t2;
            __syncthreads();
        }
        if (gid < P) g_rowP[gid] = sa[tid] - v;
        if (tid == 255) g_bsA[ch] = sa[255];
        __syncthreads();
    }
    gbar(&g_barA);
    if (blockIdx.x == 0) {
        if (tid == 0) s_cA = 0;
        __syncthreads();
        for (int base = 0; base < NPCH; base += 256) {
            int i = base + tid;
            int v = (i < NPCH) ? g_bsA[i] : 0;
            sa[tid] = v; __syncthreads();
            for (int off = 1; off < 256; off <<= 1) {
                int t2 = 0;
                if (tid >= off) t2 = sa[tid - off];
                __syncthreads();
                if (tid >= off) sa[tid] += t2;
                __syncthreads();
            }
            if (i < NPCH) g_bsA[i] = s_cA + sa[tid] - v;
            __syncthreads();
            if (tid == 0) s_cA += sa[255];
            __syncthreads();
        }
        if (tid == 0) g_rowP[P] = s_cA;
    }
    gbar(&g_barA);
    for (int p = blockIdx.x * 256 + tid; p < P; p += stride) g_rowP[p] += g_bsA[p >> 8];
    gbar(&g_barA);
    // scatter memberships into per-cluster lists
    int np = g_pair_tail; if (np > PAIRMAX) np = PAIRMAX;
    for (int i = blockIdx.x * 256 + tid; i < np; i += stride) {
        uint2 pr = g_pairs[i];
        unsigned c = pr.y;
        if (c >= (unsigned)P) continue;
        int pos = g_rowP[c] + atomicAdd(&g_cc2[c], 1);
        if (pos < PAIRMAX) g_mlist[pos] = (int)pr.x;
    }
}

// ---------------- L4: gather maxes + cluster softmax + outputs ----------------
__global__ void __launch_bounds__(256) k_gatherfinal(const float* __restrict__ x,
                                                     const void* batch,
                                                     float* __restrict__ out,
                                                     int N, int C) {
    int tid = threadIdx.x;
    int is64 = g_is64;
    int P = g_nP; if (P > PMAXP) P = PMAXP;
    __shared__ float sred[256];
    __shared__ int sm_m[256];
    for (int p = blockIdx.x; p < P; p += gridDim.x) {
        int beg = g_rowP[p], end = g_rowP[p + 1];
        float em = -1e30f;
        for (int m = beg + tid; m < end; m += 256) {
            int v = g_mlist[m];
            long long bt = ld_idx(batch, v, is64);
            em = fmaxf(em, g_e[v] / g_bsum[bt]);
        }
        sred[tid] = em; __syncthreads();
        for (int off = 128; off; off >>= 1) {
            if (tid < off) sred[tid] = fmaxf(sred[tid], sred[tid + off]);
            __syncthreads();
        }
        if (tid == 0) g_maxelevF[p] = sred[0];
        float vm = -1e30f;
        for (int mb = beg; mb < end; mb += 256) {
            int cnt = end - mb; if (cnt > 256) cnt = 256;
            __syncthreads();
            if (tid < cnt) sm_m[tid] = g_mlist[mb + tid];
            __syncthreads();
            if (tid < C) {
                for (int j = 0; j < cnt; j++)
                    vm = fmaxf(vm, x[(size_t)sm_m[j] * C + tid]);
            }
        }
        if (tid < C) g_poolmax[(size_t)p * C + tid] = vm;
        for (int ch = 256 + tid; ch < C; ch += 256) {
            float v2 = -1e30f;
            for (int m = beg; m < end; m++)
                v2 = fmaxf(v2, x[(size_t)g_mlist[m] * C + ch]);
            g_poolmax[(size_t)p * C + ch] = v2;
        }
        __syncthreads();
    }
    gbar(&g_barB);
    __shared__ unsigned smax[BMAXB];
    __shared__ float ssum[BMAXB];
    if (tid < BMAXB) smax[tid] = 0u;
    __syncthreads();
    int stride = gridDim.x * 256;
    for (int p = blockIdx.x * 256 + tid; p < P; p += stride)
        atomicMax(&smax[g_cbv[p]], encf(g_maxelevF[p]));
    __syncthreads();
    if (tid < BMAXB && smax[tid] != 0u) atomicMax(&g_cbmax[tid], smax[tid]);
    gbar(&g_barB);
    if (tid < BMAXB) ssum[tid] = 0.f;
    __syncthreads();
    for (int p = blockIdx.x * 256 + tid; p < P; p += stride) {
        float ex = expf(g_maxelevF[p] - decf(g_cbmax[g_cbv[p]]));
        g_exn[p] = ex;
        atomicAdd(&ssum[g_cbv[p]], ex);
    }
    __syncthreads();
    if (tid < BMAXB && ssum[tid] != 0.f) atomicAdd(&g_cbsum[tid], ssum[tid]);
    gbar(&g_barB);
    int warp = (blockIdx.x * 256 + tid) >> 5;
    int lane = tid & 31;
    int nw = stride >> 5;
    for (int p = warp; p < P; p += nw) {
        float normed = g_exn[p] / g_cbsum[g_cbv[p]];
        const float* mx = g_poolmax + (size_t)p * C;
        float* orow = out + (size_t)p * C;
        for (int i = lane; i < C; i += 32) orow[i] = mx[i] * normed;
        if (lane == 0) out[(size_t)P * C + p] = (float)g_cbv[p];
    }
    for (int n = blockIdx.x * 256 + tid; n < N; n += stride) {
        long long bt = ld_idx(batch, n, is64);
        out[(size_t)P * (C + 1) + n] = g_e[n] / g_bsum[bt];
    }
}

// ---------------- host launcher ----------------
extern "C" void kernel_launch(void* const* d_in, const int* in_sizes, int n_in,
                              void* d_out, int out_size) {
    const float* x  = (const float*)d_in[0];
    const void*  ei = d_in[1];
    const void*  bt = d_in[2];
    const float* W  = (const float*)d_in[3];
    const float* bb = (const float*)d_in[4];
    int N = in_sizes[2];
    int C = in_sizes[0] / (N > 0 ? N : 1);
    int E = in_sizes[1] / 2;
    float* out = (float*)d_out;
    cudaStream_t s = 0;

    int gNE = ((N > E ? N : E) + 255) / 256; if (gNE < 1) gNE = 1;
    long long zthreads = (long long)N * 32;
    int gZ = (int)((zthreads + 255) / 256); if (gZ < 1) gZ = 1;

    int sm = 148;
    cudaDeviceGetAttribute(&sm, cudaDevAttrMultiProcessorCount, 0);
    int bpmA = 1, bpmB = 1;
    cudaOccupancyMaxActiveBlocksPerMultiprocessor(&bpmA, k_bfsmega, 256, 0);
    cudaOccupancyMaxActiveBlocksPerMultiprocessor(&bpmB, k_gatherfinal, 256, 0);
    if (bpmA < 1) bpmA = 1;
    if (bpmB < 1) bpmB = 1;
    int nbA = sm * bpmA; if (nbA < 1) nbA = 1;
    int nbB = sm * bpmB; if (nbB < 1) nbB = 1;

    k_initz<<<gZ, 256, 0, s>>>(x, W, bb, bt, ei, N, C, E);
    k_ee<<<gNE, 256, 0, s>>>(ei, bt, N, E);
    k_bfsmega<<<nbA, 256, 0, s>>>(bt, N);
    k_gatherfinal<<<nbB, 256, 0, s>>>(x, bt, out, N, C);
}